// round 2
// baseline (speedup 1.0000x reference)
#include <cuda_runtime.h>
#include <math.h>

// Problem constants
#define C_    12
#define B_    64
#define HW_   65536            // 256*256
#define NPC   4194304LL        // per-channel element count = B_*HW_
#define BINS_ 1000
#define CAP   12288            // candidate buffer per (channel, quantile)
#define LCAP  2048             // per-block local candidate staging

// -------- device scratch (no allocations allowed) --------
__device__ double   g_sum[C_];
__device__ double   g_sumsq[C_];
__device__ unsigned g_minkey[C_];
__device__ unsigned g_maxkey[C_];
__device__ int      g_hist[C_ * BINS_];
__device__ int      g_win[C_ * 2 * 2];   // per (c,q): [lo_bin, hi_bin]
__device__ int      g_lrank[C_ * 2];     // local rank of global rank k within candidate set
__device__ float    g_frac[2];           // interpolation fraction per quantile
__device__ int      g_ccount[C_ * 2];    // candidate counts
__device__ unsigned g_cand[C_ * 2 * CAP];// candidate keys (order-preserving uint transform)

// order-preserving float<->uint key transform (handles negatives too)
__device__ __forceinline__ unsigned fkey(float f) {
    unsigned u = __float_as_uint(f);
    return (u & 0x80000000u) ? ~u : (u | 0x80000000u);
}
__device__ __forceinline__ float finv(unsigned k) {
    unsigned u = (k & 0x80000000u) ? (k ^ 0x80000000u) : ~k;
    return __uint_as_float(u);
}

// ================= K0: init scratch =================
__global__ void k_init() {
    int t = blockIdx.x * blockDim.x + threadIdx.x;
    int n = gridDim.x * blockDim.x;
    for (int i = t; i < C_ * BINS_; i += n) g_hist[i] = 0;
    if (t < C_) {
        g_sum[t] = 0.0; g_sumsq[t] = 0.0;
        g_minkey[t] = 0xFFFFFFFFu;
        g_maxkey[t] = 0u;
    }
    if (t < C_ * 2) g_ccount[t] = 0;
}

// ================= K1: main pass =================
// grid = B*C = 768 blocks; each block handles one [H,W] plane:
// 65536 contiguous floats of channel c, image b.
__global__ void __launch_bounds__(256) k_main(const float* __restrict__ x) {
    __shared__ int sh[BINS_];
    const int plane = blockIdx.x;              // = img*C_ + ch
    const int c = plane % C_;
    const float4* p = reinterpret_cast<const float4*>(x)
        + (size_t)plane * (HW_ / 4) + threadIdx.x;

    for (int i = threadIdx.x; i < BINS_; i += 256) sh[i] = 0;
    __syncthreads();

    float s = 0.0f, ss = 0.0f;
    float mn = __int_as_float(0x7F800000);   // +inf
    float mx = -mn;

    #pragma unroll 8
    for (int i = 0; i < 64; i++) {
        float4 v = p[i * 256];
        float a[4] = { v.x, v.y, v.z, v.w };
        #pragma unroll
        for (int j = 0; j < 4; j++) {
            float f = a[j];
            s += f;
            ss = fmaf(f, f, ss);
            mn = fminf(mn, f);
            mx = fmaxf(mx, f);
            if (f >= 0.0f && f <= 100.0f) {
                // f >= 0 here, so trunc == floor; clip to last bin
                int b = min(__float2int_rz(f * 10.0f), BINS_ - 1);
                atomicAdd(&sh[b], 1);
            }
        }
    }

    // warp reduce moments + min/max
    #pragma unroll
    for (int off = 16; off; off >>= 1) {
        s  += __shfl_down_sync(0xffffffffu, s,  off);
        ss += __shfl_down_sync(0xffffffffu, ss, off);
        mn = fminf(mn, __shfl_down_sync(0xffffffffu, mn, off));
        mx = fmaxf(mx, __shfl_down_sync(0xffffffffu, mx, off));
    }
    if ((threadIdx.x & 31) == 0) {
        atomicAdd(&g_sum[c],   (double)s);
        atomicAdd(&g_sumsq[c], (double)ss);
        atomicMin(&g_minkey[c], fkey(mn));
        atomicMax(&g_maxkey[c], fkey(mx));
    }

    __syncthreads();
    for (int i = threadIdx.x; i < BINS_; i += 256) {
        int v = sh[i];
        if (v) atomicAdd(&g_hist[c * BINS_ + i], v);
    }
}

// ================= K2: finalize stats + quantile windows =================
__global__ void __launch_bounds__(384) k_final(
    const float* __restrict__ mean_in, const float* __restrict__ var_in,
    const float* __restrict__ count_in, const float* __restrict__ minv_in,
    const float* __restrict__ maxv_in,  const float* __restrict__ hist_in,
    float* __restrict__ out)
{
    const int tid = threadIdx.x;

    // hist output = input hist + batch hist
    for (int i = tid; i < C_ * BINS_; i += 384)
        out[61 + i] = hist_in[i] + (float)g_hist[i];

    // per-channel merged stats
    if (tid < C_) {
        int c = tid;
        double bm = g_sum[c] / (double)NPC;
        double bv = (g_sumsq[c] - (double)NPC * bm * bm) / ((double)NPC - 1.0);
        double cnt = (double)count_in[0];
        double bc  = (double)B_;
        double nab = cnt + bc;
        double m_in = (double)mean_in[c], v_in = (double)var_in[c];
        double delta = bm - m_in;
        double nm = (m_in * cnt + bm * bc) / nab;
        double nv = (v_in * cnt + bv * bc + delta * delta * cnt * bc / nab) / nab;
        out[c]      = (float)nm;
        out[12 + c] = (float)nv;
        out[24 + c] = (float)sqrt(nv + 1e-8);
        out[36 + c] = fminf(minv_in[c], finv(g_minkey[c]));
        out[48 + c] = fmaxf(maxv_in[c], finv(g_maxkey[c]));
        if (c == 0) out[60] = (float)nab;
    }

    // quantile windows: warp w scans channel w's histogram cumsum
    const int w = tid >> 5, lane = tid & 31;
    if (w < C_) {
        const double p0 = (double)0.02f * (double)(NPC - 1);
        const double p1 = (double)0.98f * (double)(NPC - 1);
        const long long k0 = (long long)p0;
        const long long k1 = (long long)p1;
        if (w == 0 && lane == 0) {
            g_frac[0] = (float)(p0 - (double)k0);
            g_frac[1] = (float)(p1 - (double)k1);
        }
        long long tgt[4] = { k0, k0 + 1, k1, k1 + 1 };
        int tb[4] = { -1, -1, -1, -1 };
        long long tc[4] = { 0, 0, 0, 0 };
        long long cum = 0;
        for (int base = 0; base < BINS_; base += 32) {
            int idx = base + lane;
            int v = (idx < BINS_) ? g_hist[w * BINS_ + idx] : 0;
            int sc = v;
            #pragma unroll
            for (int off = 1; off < 32; off <<= 1) {
                int t = __shfl_up_sync(0xffffffffu, sc, off);
                if (lane >= off) sc += t;
            }
            long long cexc = cum + (long long)(sc - v);
            long long cinc = cum + (long long)sc;
            #pragma unroll
            for (int j = 0; j < 4; j++) {
                if (tb[j] < 0) {
                    unsigned bal = __ballot_sync(0xffffffffu, cinc > tgt[j]);
                    if (bal) {
                        int ln = __ffs(bal) - 1;
                        tb[j] = base + ln;
                        tc[j] = __shfl_sync(0xffffffffu, cexc, ln);
                    }
                }
            }
            cum += (long long)__shfl_sync(0xffffffffu, sc, 31);
        }
        if (lane == 0) {
            for (int j = 0; j < 4; j++) if (tb[j] < 0) tb[j] = BINS_ - 1;
            g_win[(w * 2 + 0) * 2 + 0] = tb[0];
            g_win[(w * 2 + 0) * 2 + 1] = tb[1];
            g_win[(w * 2 + 1) * 2 + 0] = tb[2];
            g_win[(w * 2 + 1) * 2 + 1] = tb[3];
            g_lrank[w * 2 + 0] = (int)(k0 - tc[0]);
            g_lrank[w * 2 + 1] = (int)(k1 - tc[2]);
        }
    }
}

// ================= K3: collect quantile-window candidates =================
// same geometry as k_main: one plane per block
__global__ void __launch_bounds__(256) k_collect(const float* __restrict__ x) {
    __shared__ float st[2][LCAP];
    __shared__ int nloc[2], basep[2];
    const int plane = blockIdx.x;
    const int c = plane % C_;
    const float4* p = reinterpret_cast<const float4*>(x)
        + (size_t)plane * (HW_ / 4) + threadIdx.x;

    if (threadIdx.x < 2) nloc[threadIdx.x] = 0;
    const int lo0 = g_win[(c * 2 + 0) * 2 + 0], hi0 = g_win[(c * 2 + 0) * 2 + 1];
    const int lo1 = g_win[(c * 2 + 1) * 2 + 0], hi1 = g_win[(c * 2 + 1) * 2 + 1];
    __syncthreads();

    #pragma unroll 8
    for (int i = 0; i < 64; i++) {
        float4 v = p[i * 256];
        float a[4] = { v.x, v.y, v.z, v.w };
        #pragma unroll
        for (int j = 0; j < 4; j++) {
            float f = a[j];
            if (f >= 0.0f && f <= 100.0f) {
                int b = min(__float2int_rz(f * 10.0f), BINS_ - 1);
                if (b >= lo0 && b <= hi0) {
                    int t = atomicAdd(&nloc[0], 1);
                    if (t < LCAP) st[0][t] = f;
                }
                if (b >= lo1 && b <= hi1) {
                    int t = atomicAdd(&nloc[1], 1);
                    if (t < LCAP) st[1][t] = f;
                }
            }
        }
    }
    __syncthreads();
    if (threadIdx.x < 2) {
        int n = min(nloc[threadIdx.x], LCAP);
        basep[threadIdx.x] = atomicAdd(&g_ccount[c * 2 + threadIdx.x], n);
    }
    __syncthreads();
    #pragma unroll
    for (int q = 0; q < 2; q++) {
        int n  = min(nloc[q], LCAP);
        int bp = basep[q];
        for (int i = threadIdx.x; i < n; i += 256) {
            int d = bp + i;
            if (d < CAP) g_cand[(c * 2 + q) * CAP + d] = fkey(st[q][i]);
        }
    }
}

// ================= K4: radix-select order statistics, interpolate =================
__global__ void __launch_bounds__(256) k_select(float* __restrict__ out) {
    __shared__ int cnt[256];
    __shared__ int sb, sr;
    const int c = blockIdx.x >> 1, q = blockIdx.x & 1;
    const unsigned* keys = &g_cand[(c * 2 + q) * CAP];
    int n = g_ccount[c * 2 + q];
    if (n > CAP) n = CAP;
    if (n < 1)  n = 1;
    const int r0 = g_lrank[c * 2 + q];

    float v[2];
    for (int sel = 0; sel < 2; sel++) {
        int r = r0 + sel;
        if (r < 0) r = 0;
        if (r >= n) r = n - 1;
        unsigned prefix = 0, mask = 0;
        for (int shift = 24; shift >= 0; shift -= 8) {
            cnt[threadIdx.x] = 0;
            __syncthreads();
            for (int i = threadIdx.x; i < n; i += 256) {
                unsigned k = keys[i];
                if ((k & mask) == prefix) atomicAdd(&cnt[(k >> shift) & 255], 1);
            }
            __syncthreads();
            if (threadIdx.x == 0) {
                int run = 0, b = 0;
                for (; b < 256; b++) {
                    if (run + cnt[b] > r) break;
                    run += cnt[b];
                }
                if (b == 256) b = 255;
                sb = b; sr = r - run;
            }
            __syncthreads();
            prefix |= ((unsigned)sb) << shift;
            mask   |= (0xFFu << shift);
            r = sr;
            __syncthreads();
        }
        v[sel] = finv(prefix);
    }
    if (threadIdx.x == 0) {
        float frac = g_frac[q];
        float pct = v[0] + frac * (v[1] - v[0]);
        out[12061 + q * 12 + c] = pct;   // pct_02 @ [12061..12072], pct_98 @ [12073..12084]
    }
}

// ================= launcher =================
extern "C" void kernel_launch(void* const* d_in, const int* in_sizes, int n_in,
                              void* d_out, int out_size) {
    const float* x        = (const float*)d_in[0];
    const float* mean_in  = (const float*)d_in[1];
    const float* var_in   = (const float*)d_in[2];
    const float* count_in = (const float*)d_in[3];
    const float* minv_in  = (const float*)d_in[4];
    const float* maxv_in  = (const float*)d_in[5];
    const float* hist_in  = (const float*)d_in[6];
    float* out = (float*)d_out;

    k_init<<<48, 256>>>();
    k_main<<<B_ * C_, 256>>>(x);
    k_final<<<1, 384>>>(mean_in, var_in, count_in, minv_in, maxv_in, hist_in, out);
    k_collect<<<B_ * C_, 256>>>(x);
    k_select<<<C_ * 2, 256>>>(out);
}